// round 5
// baseline (speedup 1.0000x reference)
#include <cuda_runtime.h>
#include <math.h>

// ---------------------------------------------------------------------------
// BFM factorization-machine scoring, sparsity-aware, single fused kernel.
//   y = w0 + x.w_bias + u.t + t.b + 0.5*(b.b - sum_b_sq) + u.b
//   out = sigmoid(y * delta)
// Thin scan (1 float4/thread); threads that find a nonzero immediately
// scatter-accumulate (RED.F32) wb + the 64-float embedding row into global
// accumulators. Last block reduces 3x64 + 2 scalars and writes out.
// ---------------------------------------------------------------------------

#define KDIM 64
#define TPB  512

__device__ float g_u[KDIM];
__device__ float g_t[KDIM];
__device__ float g_b[KDIM];
__device__ float g_bias = 0.f;
__device__ float g_absq = 0.f;
__device__ int   g_done = 0;

// Rare path: keep it out of the hot path's register budget.
__device__ __noinline__ void process_nz(int idx, float v,
                                        const float* __restrict__ wb,
                                        const float* __restrict__ uV,
                                        const float* __restrict__ tV,
                                        const float* __restrict__ bV,
                                        int N, int M)
{
    atomicAdd(&g_bias, v * __ldg(wb + idx));

    const float* row;
    float* acc;
    bool isB = false;
    if (idx < N)          { row = uV + (size_t)idx * KDIM;           acc = g_u; }
    else if (idx < N + M) { row = tV + (size_t)(idx - N) * KDIM;     acc = g_t; }
    else                  { row = bV + (size_t)(idx - N - M) * KDIM; acc = g_b; isB = true; }

    float absq = 0.f;
    #pragma unroll 4
    for (int c = 0; c < KDIM / 4; ++c) {
        float4 e = reinterpret_cast<const float4*>(row)[c];
        atomicAdd(acc + 4 * c + 0, v * e.x);
        atomicAdd(acc + 4 * c + 1, v * e.y);
        atomicAdd(acc + 4 * c + 2, v * e.z);
        atomicAdd(acc + 4 * c + 3, v * e.w);
        if (isB) absq += e.x * e.x + e.y * e.y + e.z * e.z + e.w * e.w;
    }
    if (isB) atomicAdd(&g_absq, v * absq);
}

__global__ void __launch_bounds__(TPB)
bfm_kernel(const float* __restrict__ x,
           const float* __restrict__ wb,
           const float* __restrict__ w0,
           const float* __restrict__ delta,
           const float* __restrict__ uV,
           const float* __restrict__ tV,
           const float* __restrict__ bV,
           float* __restrict__ out,
           int out_size, int P4, int P, int N, int M, int nblocks)
{
    const int tid = threadIdx.x;
    const int i = blockIdx.x * TPB + tid;

    // ---- thin scan: one coalesced float4 per thread ----
    if (i < P4) {
        float4 xv = reinterpret_cast<const float4*>(x)[i];
        if ((xv.x != 0.f) | (xv.y != 0.f) | (xv.z != 0.f) | (xv.w != 0.f)) {
            int base = i * 4;
            if (xv.x != 0.f) process_nz(base + 0, xv.x, wb, uV, tV, bV, N, M);
            if (xv.y != 0.f) process_nz(base + 1, xv.y, wb, uV, tV, bV, N, M);
            if (xv.z != 0.f) process_nz(base + 2, xv.z, wb, uV, tV, bV, N, M);
            if (xv.w != 0.f) process_nz(base + 3, xv.w, wb, uV, tV, bV, N, M);
        }
    }
    // tail (P not a multiple of 4)
    if (blockIdx.x == 0 && tid == 0) {
        for (int r = P4 * 4; r < P; ++r) {
            float v = x[r];
            if (v != 0.f) process_nz(r, v, wb, uV, tV, bV, N, M);
        }
    }

    // ---- last-block election (tid0-only fences) ----
    __syncthreads();
    __shared__ int s_last;
    if (tid == 0) {
        __threadfence();                      // release this block's REDs
        int d = atomicAdd(&g_done, 1);
        s_last = (d == nblocks - 1);
        if (s_last) __threadfence();          // acquire all blocks' REDs
    }
    __syncthreads();
    if (!s_last) return;

    // ---- finisher: one L2 round-trip + one warp tree ----
    __shared__ float s_part[2];
    __shared__ float s_bias, s_absq;
    if (tid == 64) { s_bias = __ldcg(&g_bias); s_absq = __ldcg(&g_absq); }
    if (tid < KDIM) {
        float u = __ldcg(&g_u[tid]);
        float t = __ldcg(&g_t[tid]);
        float b = __ldcg(&g_b[tid]);
        float lane = u * t + t * b + u * b + 0.5f * b * b;
        #pragma unroll
        for (int off = 16; off > 0; off >>= 1)
            lane += __shfl_down_sync(0xffffffffu, lane, off);
        if ((tid & 31) == 0) s_part[tid >> 5] = lane;
        g_u[tid] = 0.f; g_t[tid] = 0.f; g_b[tid] = 0.f;  // reset for next replay
    }
    __syncthreads();
    if (tid == 0) {
        float y = w0[0] + s_bias + s_part[0] + s_part[1] - 0.5f * s_absq;
        float z = y * delta[0];
        float r = 1.f / (1.f + expf(-z));
        for (int q = 0; q < out_size; ++q) out[q] = r;
        g_bias = 0.f; g_absq = 0.f; g_done = 0;          // reset for next replay
    }
}

extern "C" void kernel_launch(void* const* d_in, const int* in_sizes, int n_in,
                              void* d_out, int out_size)
{
    const float* x     = (const float*)d_in[0];
    const float* delta = (const float*)d_in[1];
    /* pmi = d_in[2] unused */
    const float* w0    = (const float*)d_in[3];
    const float* wb    = (const float*)d_in[4];
    const float* uV    = (const float*)d_in[5];
    const float* tV    = (const float*)d_in[6];
    const float* bV    = (const float*)d_in[7];

    int P  = in_sizes[0];
    int N  = in_sizes[5] / KDIM;
    int M  = in_sizes[6] / KDIM;
    int P4 = P / 4;
    int blocks = (P4 + TPB - 1) / TPB;

    bfm_kernel<<<blocks, TPB>>>(x, wb, w0, delta, uV, tV, bV,
                                (float*)d_out, out_size, P4, P, N, M, blocks);
}

// round 6
// speedup vs baseline: 1.5117x; 1.5117x over previous
#include <cuda_runtime.h>
#include <math.h>

// ---------------------------------------------------------------------------
// BFM factorization-machine scoring, sparsity-aware, single fused kernel.
//   y = w0 + x.w_bias + u.t + t.b + 0.5*(b.b - sum_b_sq) + u.b
//   out = sigmoid(y * delta)
// Thin scan compacts nonzeros of x into a global list and scatter-accumulates
// the bias term. Last block to finish gathers the ~66 embedding rows
// (all loads in flight, L2-hot) and reduces with 3 barriers.
// ---------------------------------------------------------------------------

#define KDIM 64
#define TPB  512
#define LIST_CAP 1024   // smem staging capacity; falls back to global if exceeded

__device__ int   g_nnz  = 0;
__device__ int   g_done = 0;
__device__ float g_bias = 0.f;
__device__ int   g_idx[2100000];
__device__ float g_val[2100000];

__global__ void __launch_bounds__(TPB)
bfm_kernel(const float* __restrict__ x,
           const float* __restrict__ wb,
           const float* __restrict__ w0,
           const float* __restrict__ delta,
           const float* __restrict__ uV,
           const float* __restrict__ tV,
           const float* __restrict__ bV,
           float* __restrict__ out,
           int out_size, int P4, int P, int N, int M, int nblocks)
{
    const int tid = threadIdx.x;
    const int i = blockIdx.x * TPB + tid;

    // ---- thin scan: one coalesced float4 per thread ----
    if (i < P4) {
        float4 xv = reinterpret_cast<const float4*>(x)[i];
        if ((xv.x != 0.f) | (xv.y != 0.f) | (xv.z != 0.f) | (xv.w != 0.f)) {
            int base = i * 4;
            if (xv.x != 0.f) { int p = atomicAdd(&g_nnz, 1); g_idx[p] = base + 0; g_val[p] = xv.x;
                               atomicAdd(&g_bias, xv.x * __ldg(wb + base + 0)); }
            if (xv.y != 0.f) { int p = atomicAdd(&g_nnz, 1); g_idx[p] = base + 1; g_val[p] = xv.y;
                               atomicAdd(&g_bias, xv.y * __ldg(wb + base + 1)); }
            if (xv.z != 0.f) { int p = atomicAdd(&g_nnz, 1); g_idx[p] = base + 2; g_val[p] = xv.z;
                               atomicAdd(&g_bias, xv.z * __ldg(wb + base + 2)); }
            if (xv.w != 0.f) { int p = atomicAdd(&g_nnz, 1); g_idx[p] = base + 3; g_val[p] = xv.w;
                               atomicAdd(&g_bias, xv.w * __ldg(wb + base + 3)); }
        }
    }
    // tail (P not a multiple of 4)
    if (blockIdx.x == 0 && tid == 0) {
        for (int r = P4 * 4; r < P; ++r) {
            float v = x[r];
            if (v != 0.f) { int p = atomicAdd(&g_nnz, 1); g_idx[p] = r; g_val[p] = v;
                            atomicAdd(&g_bias, v * __ldg(wb + r)); }
        }
    }

    // ---- last-block election (tid0-only fences) ----
    __syncthreads();
    __shared__ int s_last;
    if (tid == 0) {
        __threadfence();                      // release this block's writes
        int d = atomicAdd(&g_done, 1);
        s_last = (d == nblocks - 1);
        if (s_last) __threadfence();          // acquire all blocks' writes
    }
    __syncthreads();
    if (!s_last) return;

    // ---- finisher ----
    __shared__ int   s_idx[LIST_CAP];
    __shared__ float s_val[LIST_CAP];
    __shared__ float sA[TPB], sB[TPB], sC[TPB], sD[TPB];
    __shared__ float s_warp[2];

    const int nnz = g_nnz;
    const bool in_smem = (nnz <= LIST_CAP);
    if (in_smem) {
        for (int q = tid; q < nnz; q += TPB) { s_idx[q] = g_idx[q]; s_val[q] = g_val[q]; }
    }
    __syncthreads();                          // barrier 1

    // gather: 64 lanes x 8 row-groups, branchless, all loads in flight
    const int k  = tid & (KDIM - 1);
    const int g8 = tid >> 6;
    float au = 0.f, at_ = 0.f, ab = 0.f, absq = 0.f;
    #pragma unroll 4
    for (int j = g8; j < nnz; j += 8) {
        int idx; float v;
        if (in_smem) { idx = s_idx[j]; v = s_val[j]; }
        else         { idx = g_idx[j]; v = g_val[j]; }
        bool isU = idx < N;
        bool isT = !isU && (idx < N + M);
        bool isB = !isU && !isT;
        const float* p = isU ? (uV + (size_t)idx * KDIM)
                       : isT ? (tV + (size_t)(idx - N) * KDIM)
                             : (bV + (size_t)(idx - N - M) * KDIM);
        float e  = p[k];
        float ve = v * e;
        au   += isU ? ve : 0.f;
        at_  += isT ? ve : 0.f;
        ab   += isB ? ve : 0.f;
        absq += isB ? ve * e : 0.f;
    }
    sA[tid] = au; sB[tid] = at_; sC[tid] = ab; sD[tid] = absq;
    __syncthreads();                          // barrier 2

    if (tid < KDIM) {
        float u = 0.f, t = 0.f, b = 0.f, aq = 0.f;
        #pragma unroll
        for (int q = 0; q < 8; ++q) {
            u  += sA[tid + 64 * q];
            t  += sB[tid + 64 * q];
            b  += sC[tid + 64 * q];
            aq += sD[tid + 64 * q];
        }
        float lane = u * t + t * b + u * b + 0.5f * b * b - 0.5f * aq;
        #pragma unroll
        for (int off = 16; off > 0; off >>= 1)
            lane += __shfl_down_sync(0xffffffffu, lane, off);
        if ((tid & 31) == 0) s_warp[tid >> 5] = lane;
    }
    __syncthreads();                          // barrier 3

    if (tid == 0) {
        float y = w0[0] + __ldcg(&g_bias) + s_warp[0] + s_warp[1];
        float z = y * delta[0];
        float r = 1.f / (1.f + expf(-z));
        for (int q = 0; q < out_size; ++q) out[q] = r;
        g_nnz = 0; g_done = 0; g_bias = 0.f;  // reset for next replay
    }
}

extern "C" void kernel_launch(void* const* d_in, const int* in_sizes, int n_in,
                              void* d_out, int out_size)
{
    const float* x     = (const float*)d_in[0];
    const float* delta = (const float*)d_in[1];
    /* pmi = d_in[2] unused */
    const float* w0    = (const float*)d_in[3];
    const float* wb    = (const float*)d_in[4];
    const float* uV    = (const float*)d_in[5];
    const float* tV    = (const float*)d_in[6];
    const float* bV    = (const float*)d_in[7];

    int P  = in_sizes[0];
    int N  = in_sizes[5] / KDIM;
    int M  = in_sizes[6] / KDIM;
    int P4 = P / 4;
    int blocks = (P4 + TPB - 1) / TPB;

    bfm_kernel<<<blocks, TPB>>>(x, wb, w0, delta, uV, tV, bV,
                                (float*)d_out, out_size, P4, P, N, M, blocks);
}

// round 7
// speedup vs baseline: 1.7232x; 1.1399x over previous
#include <cuda_runtime.h>
#include <math.h>

// ---------------------------------------------------------------------------
// BFM factorization-machine scoring, sparsity-aware, single fused kernel.
//   y = w0 + x.w_bias + u.t + t.b + 0.5*(b.b - sum_b_sq) + u.b
//   out = sigmoid(y * delta)
// Single-wave grid (148 SMs x 4 CTAs x 512 thr), 2 float4 loads per thread
// issued back-to-back (MLP=2). Nonzero discoverers append to a global list
// and scatter the bias term. Last block to arrive gathers the ~66 embedding
// rows straight from L2 (warp-uniform list reads) and reduces in 2 barriers.
// ---------------------------------------------------------------------------

#define KDIM 64
#define TPB  512
#define CTAS_PER_SM 4
#define NSM  148

__device__ int   g_nnz  = 0;
__device__ int   g_done = 0;
__device__ float g_bias = 0.f;
__device__ int   g_idx[2100000];
__device__ float g_val[2100000];

__device__ __forceinline__ void emit_nz(int idx, float v, const float* __restrict__ wb)
{
    int p = atomicAdd(&g_nnz, 1);
    g_idx[p] = idx;
    g_val[p] = v;
    atomicAdd(&g_bias, v * __ldg(wb + idx));
}

__global__ void __launch_bounds__(TPB, CTAS_PER_SM)
bfm_kernel(const float* __restrict__ x,
           const float* __restrict__ wb,
           const float* __restrict__ w0,
           const float* __restrict__ delta,
           const float* __restrict__ uV,
           const float* __restrict__ tV,
           const float* __restrict__ bV,
           float* __restrict__ out,
           int out_size, int P4, int P, int N, int M, int nblocks)
{
    const int tid = threadIdx.x;
    const int stride = nblocks * TPB;
    const int i0 = blockIdx.x * TPB + tid;
    const int i1 = i0 + stride;

    // ---- scan: two coalesced float4 loads, both in flight ----
    float4 a, b;
    bool ok0 = i0 < P4, ok1 = i1 < P4;
    if (ok0) a = reinterpret_cast<const float4*>(x)[i0];
    if (ok1) b = reinterpret_cast<const float4*>(x)[i1];

    if (ok0 && ((a.x != 0.f) | (a.y != 0.f) | (a.z != 0.f) | (a.w != 0.f))) {
        int base = i0 * 4;
        if (a.x != 0.f) emit_nz(base + 0, a.x, wb);
        if (a.y != 0.f) emit_nz(base + 1, a.y, wb);
        if (a.z != 0.f) emit_nz(base + 2, a.z, wb);
        if (a.w != 0.f) emit_nz(base + 3, a.w, wb);
    }
    if (ok1 && ((b.x != 0.f) | (b.y != 0.f) | (b.z != 0.f) | (b.w != 0.f))) {
        int base = i1 * 4;
        if (b.x != 0.f) emit_nz(base + 0, b.x, wb);
        if (b.y != 0.f) emit_nz(base + 1, b.y, wb);
        if (b.z != 0.f) emit_nz(base + 2, b.z, wb);
        if (b.w != 0.f) emit_nz(base + 3, b.w, wb);
    }
    // tail (P not a multiple of 4)
    if (blockIdx.x == 0 && tid == 0) {
        for (int r = P4 * 4; r < P; ++r) {
            float v = x[r];
            if (v != 0.f) emit_nz(r, v, wb);
        }
    }

    // ---- last-block election (tid0-only fences) ----
    __syncthreads();
    __shared__ int s_last;
    if (tid == 0) {
        __threadfence();                      // release this block's writes
        int d = atomicAdd(&g_done, 1);
        s_last = (d == nblocks - 1);
        if (s_last) __threadfence();          // acquire all blocks' writes
    }
    __syncthreads();
    if (!s_last) return;

    // ---- finisher: gather straight from L2 (warp-uniform list reads) ----
    __shared__ float sA[TPB], sB[TPB], sC[TPB], sD[TPB];
    __shared__ float s_warp[2];

    const int nnz = g_nnz;
    const int k  = tid & (KDIM - 1);
    const int g8 = tid >> 6;
    float au = 0.f, at_ = 0.f, ab = 0.f, absq = 0.f;
    #pragma unroll 4
    for (int j = g8; j < nnz; j += 8) {
        int   idx = g_idx[j];                 // uniform across warp -> broadcast
        float v   = g_val[j];
        bool isU = idx < N;
        bool isT = !isU && (idx < N + M);
        bool isB = !isU && !isT;
        const float* p = isU ? (uV + (size_t)idx * KDIM)
                       : isT ? (tV + (size_t)(idx - N) * KDIM)
                             : (bV + (size_t)(idx - N - M) * KDIM);
        float e  = p[k];
        float ve = v * e;
        au   += isU ? ve : 0.f;
        at_  += isT ? ve : 0.f;
        ab   += isB ? ve : 0.f;
        absq += isB ? ve * e : 0.f;
    }
    sA[tid] = au; sB[tid] = at_; sC[tid] = ab; sD[tid] = absq;
    __syncthreads();                          // barrier 1

    if (tid < KDIM) {
        float u = 0.f, t = 0.f, bb = 0.f, aq = 0.f;
        #pragma unroll
        for (int q = 0; q < 8; ++q) {
            u  += sA[tid + 64 * q];
            t  += sB[tid + 64 * q];
            bb += sC[tid + 64 * q];
            aq += sD[tid + 64 * q];
        }
        float lane = u * t + t * bb + u * bb + 0.5f * bb * bb - 0.5f * aq;
        #pragma unroll
        for (int off = 16; off > 0; off >>= 1)
            lane += __shfl_down_sync(0xffffffffu, lane, off);
        if ((tid & 31) == 0) s_warp[tid >> 5] = lane;
    }
    __syncthreads();                          // barrier 2

    if (tid == 0) {
        float y = w0[0] + g_bias + s_warp[0] + s_warp[1];
        float z = y * delta[0];
        float r = 1.f / (1.f + expf(-z));
        for (int q = 0; q < out_size; ++q) out[q] = r;
        g_nnz = 0; g_done = 0; g_bias = 0.f;  // reset for next replay
    }
}

extern "C" void kernel_launch(void* const* d_in, const int* in_sizes, int n_in,
                              void* d_out, int out_size)
{
    const float* x     = (const float*)d_in[0];
    const float* delta = (const float*)d_in[1];
    /* pmi = d_in[2] unused */
    const float* w0    = (const float*)d_in[3];
    const float* wb    = (const float*)d_in[4];
    const float* uV    = (const float*)d_in[5];
    const float* tV    = (const float*)d_in[6];
    const float* bV    = (const float*)d_in[7];

    int P  = in_sizes[0];
    int N  = in_sizes[5] / KDIM;
    int M  = in_sizes[6] / KDIM;
    int P4 = P / 4;

    int blocks = NSM * CTAS_PER_SM;           // single wave
    // ensure coverage: each thread handles 2 float4s
    int needed = (P4 + 2 * TPB - 1) / (2 * TPB);
    if (blocks < needed) blocks = needed;

    bfm_kernel<<<blocks, TPB>>>(x, wb, w0, delta, uV, tV, bV,
                                (float*)d_out, out_size, P4, P, N, M, blocks);
}